// round 1
// baseline (speedup 1.0000x reference)
#include <cuda_runtime.h>

// out = 1 - log10(sqrt(N*(x-y)^2) + 1),  N = 1024^2  =>  1 - log10(1024*|x-y| + 1)
// Pure elementwise, HBM-bound: 2 fp32 in + 1 fp32 out, 33.5M elems.

__global__ void __launch_bounds__(256) jsim_kernel_v4(
    const float4* __restrict__ x,
    const float4* __restrict__ y,
    float4* __restrict__ out,
    int n4)
{
    int i = blockIdx.x * blockDim.x + threadIdx.x;
    if (i >= n4) return;

    float4 a = x[i];
    float4 b = y[i];
    float4 r;

    r.x = 1.0f - __log10f(fmaf(1024.0f, fabsf(a.x - b.x), 1.0f));
    r.y = 1.0f - __log10f(fmaf(1024.0f, fabsf(a.y - b.y), 1.0f));
    r.z = 1.0f - __log10f(fmaf(1024.0f, fabsf(a.z - b.z), 1.0f));
    r.w = 1.0f - __log10f(fmaf(1024.0f, fabsf(a.w - b.w), 1.0f));

    out[i] = r;
}

// Tail kernel in case n % 4 != 0 (not the case here, but keep it correct/general).
__global__ void jsim_kernel_tail(
    const float* __restrict__ x,
    const float* __restrict__ y,
    float* __restrict__ out,
    int start, int n)
{
    int i = start + blockIdx.x * blockDim.x + threadIdx.x;
    if (i >= n) return;
    out[i] = 1.0f - __log10f(fmaf(1024.0f, fabsf(x[i] - y[i]), 1.0f));
}

extern "C" void kernel_launch(void* const* d_in, const int* in_sizes, int n_in,
                              void* d_out, int out_size)
{
    const float* x = (const float*)d_in[0];
    const float* y = (const float*)d_in[1];
    float* out = (float*)d_out;

    int n = in_sizes[0];
    int n4 = n / 4;

    if (n4 > 0) {
        int threads = 256;
        int blocks = (n4 + threads - 1) / threads;
        jsim_kernel_v4<<<blocks, threads>>>(
            (const float4*)x, (const float4*)y, (float4*)out, n4);
    }

    int rem_start = n4 * 4;
    int rem = n - rem_start;
    if (rem > 0) {
        jsim_kernel_tail<<<1, 256>>>(x, y, out, rem_start, n);
    }
}